// round 8
// baseline (speedup 1.0000x reference)
#include <cuda_runtime.h>

#define THREADS 128
#define CPB     128
#define MAX_PART 2048

__device__ float g_partials[MAX_PART];
__device__ unsigned int g_count = 0;   // wraps to 0 each replay via atomicInc

__global__ __launch_bounds__(THREADS) void yolo_loss_kernel(
    const float* __restrict__ pred,   // [n_cells, 30]
    const float* __restrict__ targ,   // [n_cells, 25]
    long n_cells,
    long n_chunks,
    float* __restrict__ out)
{
    __shared__ __align__(16) float sPc[CPB * 30];   // compacted present P rows
    __shared__ __align__(16) float sTc[CPB * 25];   // compacted present T rows
    __shared__ int    s_list[CPB];
    __shared__ float2 s_c12[CPB];
    __shared__ int    wcnt[THREADS / 32];

    const int tid  = threadIdx.x;
    const int lane = tid & 31;
    const int wid  = tid >> 5;
    const long grid = gridDim.x;

    float acc = 0.0f;

    for (long chunk = blockIdx.x; chunk < n_chunks; chunk += grid) {
        const long cb = chunk * CPB;
        const int cells = (int)min((long)CPB, n_cells - cb);
        const bool valid = tid < cells;

        // ---- phase 1: confidence gather (only always-needed sectors) ----
        float tc = 0.0f, c1 = 0.0f, c2 = 0.0f;
        if (valid) {
            long cell = cb + tid;
            tc = __ldg(targ + cell * 25 + 4);
            c1 = __ldg(pred + cell * 30 + 4);
            c2 = __ldg(pred + cell * 30 + 9);
        }
        bool present = valid && (tc == 1.0f);
        if (valid && !present)
            acc += 0.5f * fmaf(c1, c1, c2 * c2);   // absent term: done, no more bytes

        // ---- phase 2: compact present cell indices ----
        unsigned m = __ballot_sync(0xFFFFFFFFu, present);
        int rank = __popc(m & ((1u << lane) - 1));
        if (lane == 0) wcnt[wid] = __popc(m);
        __syncthreads();
        int base = 0;
        #pragma unroll
        for (int w = 0; w < THREADS / 32; ++w)
            if (w < wid) base += wcnt[w];
        int count = wcnt[0] + wcnt[1] + wcnt[2] + wcnt[3];
        if (present) {
            int pos = base + rank;
            s_list[pos] = tid;
            s_c12[pos]  = make_float2(c1, c2);
        }
        __syncthreads();

        // ---- phase 3: block-wide flat fetch of present rows (coalesced runs) ----
        {
            int npf = count * 30;
            #pragma unroll 4
            for (int i = tid; i < npf; i += THREADS) {
                int c = i / 30;
                int e = i - c * 30;
                sPc[i] = __ldg(pred + (cb + s_list[c]) * 30 + e);
            }
            int ntf = count * 25;
            #pragma unroll 4
            for (int i = tid; i < ntf; i += THREADS) {
                int c = i / 25;
                int e = i - c * 25;
                sTc[i] = __ldg(targ + (cb + s_list[c]) * 25 + e);
            }
        }
        __syncthreads();

        // ---- phase 4: per-thread present-cell loss from compacted smem ----
        if (tid < count) {
            const float* P = sPc + tid * 30;
            const float* T = sTc + tid * 25;
            float pc1 = s_c12[tid].x, pc2 = s_c12[tid].y;
            bool r1 = (pc1 > pc2);

            float dobj = (r1 ? pc1 : pc2) - 1.0f;   // tc == 1 for present cells
            float loss = dobj * dobj;

            float cls = 0.0f;
            #pragma unroll
            for (int i = 0; i < 20; ++i) {
                float d = P[10 + i] - T[5 + i];
                cls = fmaf(d, d, cls);
            }

            int o = r1 ? 0 : 5;
            float box = 0.0f;
            #pragma unroll
            for (int i = 0; i < 2; ++i) {
                float d = P[o + i] - T[i];
                box = fmaf(d, d, box);
            }
            #pragma unroll
            for (int i = 0; i < 2; ++i) {
                float d = sqrtf(P[o + 2 + i]) - sqrtf(T[2 + i]);
                box = fmaf(d, d, box);
            }
            acc += loss + cls + 5.0f * box;
        }
        __syncthreads();   // smem reuse safety for next chunk
    }

    // ---- block reduction ----
    #pragma unroll
    for (int off = 16; off > 0; off >>= 1)
        acc += __shfl_xor_sync(0xFFFFFFFFu, acc, off);

    __shared__ float wsum[THREADS / 32];
    if (lane == 0) wsum[wid] = acc;
    __syncthreads();

    __shared__ int s_last;
    if (tid == 0) {
        g_partials[blockIdx.x] = wsum[0] + wsum[1] + wsum[2] + wsum[3];
        __threadfence();
        unsigned old = atomicInc(&g_count, gridDim.x - 1);
        s_last = (old == gridDim.x - 1) ? 1 : 0;
    }
    __syncthreads();

    // ---- last-arriving block: final reduction ----
    if (s_last) {
        __threadfence();
        double d = 0.0;
        for (int i = tid; i < (int)gridDim.x; i += THREADS)
            d += (double)__ldcg(&g_partials[i]);
        #pragma unroll
        for (int off = 16; off > 0; off >>= 1)
            d += __shfl_xor_sync(0xFFFFFFFFu, d, off);
        __shared__ double dsum[THREADS / 32];
        if (lane == 0) dsum[wid] = d;
        __syncthreads();
        if (tid == 0)
            out[0] = (float)(dsum[0] + dsum[1] + dsum[2] + dsum[3]);
    }
}

extern "C" void kernel_launch(void* const* d_in, const int* in_sizes, int n_in,
                              void* d_out, int out_size) {
    const float* pred = (const float*)d_in[0];   // [B, 1470]
    const float* targ = (const float*)d_in[1];   // [B, 1225]
    float* out = (float*)d_out;

    long B = (long)in_sizes[0] / 1470;
    long n_cells = B * 49;
    long n_chunks = (n_cells + CPB - 1) / CPB;

    long blocks = 148L * 7;                      // 29.8 KB smem -> 7 blocks/SM
    if (blocks > n_chunks) blocks = n_chunks;
    if (blocks > MAX_PART) blocks = MAX_PART;

    yolo_loss_kernel<<<(unsigned)blocks, THREADS>>>(pred, targ, n_cells, n_chunks, out);
}